// round 14
// baseline (speedup 1.0000x reference)
#include <cuda_runtime.h>

// Fused maxpool-argmax + sigma gather. BW is pinned at ~5.2-5.3 TB/s across
// all request-shape/occupancy/MLP variants (R5-R13) => gather is at its
// practical DRAM roofline. This round optimizes wave structure only:
//   - grid 1024 x 32 rows/block @ 8 CTAs/SM -> single wave (1024 <= 1184),
//     no 43%-full second wave as in R13's grid=2048.
//   - half as many pool prologues (argmax recompute) as R13.
// Access pattern unchanged (proven best): thread j <-> output column j
// (warp picks span <=4 lines), 8-deep independent LDG batches, .cs both ways.
//
// Grid: 128 bc * 8 chunks = 1024 blocks, 256 threads.
__global__ __launch_bounds__(256, 8)
void fused_pool_gather_kernel(const float* __restrict__ mu,
                              const float* __restrict__ sigma,
                              float* __restrict__ out_mu,
                              float* __restrict__ out_sig) {
    __shared__ int scol[256];

    const int bc    = blockIdx.x >> 3;    // 0..127
    const int chunk = blockIdx.x & 7;     // 0..7 (32 output rows each)
    const int tid   = threadIdx.x;        // output column j

    // ---- pool/argmax for window `tid` (mu: 4KB/bc, L2-resident) ----
    {
        const int ho = tid >> 4;
        const int wo = tid & 15;
        const float* base = mu + (size_t)bc * 1024;
        const int r0 = 2 * ho;
        const int c0 = 2 * wo;

        const float v0 = base[r0 * 32 + c0];
        const float v1 = base[r0 * 32 + c0 + 1];
        const float v2 = base[(r0 + 1) * 32 + c0];
        const float v3 = base[(r0 + 1) * 32 + c0 + 1];

        float m = v0; int k = 0;
        if (v1 > m) { m = v1; k = 1; }    // strict >: first-max (jnp.argmax)
        if (v2 > m) { m = v2; k = 2; }
        if (v3 > m) { m = v3; k = 3; }

        scol[tid] = (r0 + (k >> 1)) * 32 + (c0 + (k & 1));
        if (chunk == 0) out_mu[bc * 256 + tid] = m;
    }
    __syncthreads();

    // ---- gather: out[i][tid] = sigma[bc][scol[i]][scol[tid]] ----
    const int    cj = scol[tid];
    const float* sb = sigma   + ((size_t)bc << 20);
    float*       ob = out_sig + (size_t)bc * 65536 + tid;
    const int    i0 = chunk * 32;

    #pragma unroll
    for (int b = 0; b < 4; ++b) {
        const int ibase = i0 + b * 8;
        float v[8];
        // 8 independent scattered LDGs back-to-back (row idx broadcast via LDS).
        #pragma unroll
        for (int t = 0; t < 8; ++t)
            v[t] = __ldcs(sb + ((size_t)scol[ibase + t] << 10) + cj);
        // 8 coalesced streaming stores (full 128B line per warp-STG).
        #pragma unroll
        for (int t = 0; t < 8; ++t)
            __stcs(ob + (size_t)(ibase + t) * 256, v[t]);
    }
}

extern "C" void kernel_launch(void* const* d_in, const int* in_sizes, int n_in,
                              void* d_out, int out_size) {
    const float* mu    = (const float*)d_in[0];
    const float* sigma = (const float*)d_in[1];
    if (n_in >= 2 && in_sizes[0] > in_sizes[1]) {
        sigma = (const float*)d_in[0];
        mu    = (const float*)d_in[1];
    }

    float* out_mu  = (float*)d_out;            // 32768 elements
    float* out_sig = out_mu + 32768;           // 8388608 elements

    fused_pool_gather_kernel<<<1024, 256>>>(mu, sigma, out_mu, out_sig);
}

// round 15
// speedup vs baseline: 1.1098x; 1.1098x over previous
#include <cuda_runtime.h>

// Fused maxpool-argmax + sigma gather — consolidated best-of configuration.
//
// Roofline note: across R5-R14 (scatter/stream/staged, occ 44-84%, MLP 4-16)
// bandwidth is pinned at 5.0-5.3 TB/s with byte-minimal traffic (~155 MB:
// every 32B sector of the 256 distinct selected rows is needed; zero reuse).
// This is the practical DRAM ceiling for this scattered-read + stream-write
// mix. Config below combines the empirically fastest elements:
//   - grid 2048 (16 rows/chunk): best total (R13); fine CTAs smooth spread.
//   - R6 codegen: 8 LDS index prefetch -> 8 independent __ldcs -> 8 plain STG
//     (fastest measured kernel, 26.98us).
//   - thread j <-> output column j (warp picks span <=4 lines; R12 proved
//     wider spans cost 4x L1tex wavefronts).
//
// Grid: 128 bc * 16 chunks = 2048 blocks, 256 threads.
__global__ __launch_bounds__(256, 8)
void fused_pool_gather_kernel(const float* __restrict__ mu,
                              const float* __restrict__ sigma,
                              float* __restrict__ out_mu,
                              float* __restrict__ out_sig) {
    __shared__ int scol[256];

    const int bc    = blockIdx.x >> 4;    // 0..127
    const int chunk = blockIdx.x & 15;    // 0..15 (16 output rows each)
    const int tid   = threadIdx.x;        // output column j

    // ---- pool/argmax for window `tid` (mu: 4KB/bc, L2-resident) ----
    {
        const int ho = tid >> 4;
        const int wo = tid & 15;
        const float* base = mu + (size_t)bc * 1024;
        const int r0 = 2 * ho;
        const int c0 = 2 * wo;

        const float v0 = base[r0 * 32 + c0];
        const float v1 = base[r0 * 32 + c0 + 1];
        const float v2 = base[(r0 + 1) * 32 + c0];
        const float v3 = base[(r0 + 1) * 32 + c0 + 1];

        float m = v0; int k = 0;
        if (v1 > m) { m = v1; k = 1; }    // strict >: first-max (jnp.argmax)
        if (v2 > m) { m = v2; k = 2; }
        if (v3 > m) { m = v3; k = 3; }

        scol[tid] = (r0 + (k >> 1)) * 32 + (c0 + (k & 1));
        if (chunk == 0) out_mu[bc * 256 + tid] = m;
    }
    __syncthreads();

    // ---- gather: out[i][tid] = sigma[bc][scol[i]][scol[tid]] ----
    const int    cj = scol[tid];
    const float* sb = sigma   + ((size_t)bc << 20);
    float*       ob = out_sig + (size_t)bc * 65536 + tid;
    const int    i0 = chunk * 16;

    #pragma unroll
    for (int b = 0; b < 2; ++b) {
        const int ibase = i0 + b * 8;
        int r[8];
        #pragma unroll
        for (int t = 0; t < 8; ++t)        // index prefetch (broadcast LDS)
            r[t] = scol[ibase + t];

        float v[8];
        #pragma unroll
        for (int t = 0; t < 8; ++t)        // 8 independent scattered LDGs
            v[t] = __ldcs(sb + ((size_t)r[t] << 10) + cj);

        #pragma unroll
        for (int t = 0; t < 8; ++t)        // 8 coalesced plain STG.32
            ob[(size_t)(ibase + t) * 256] = v[t];
    }
}

extern "C" void kernel_launch(void* const* d_in, const int* in_sizes, int n_in,
                              void* d_out, int out_size) {
    const float* mu    = (const float*)d_in[0];
    const float* sigma = (const float*)d_in[1];
    if (n_in >= 2 && in_sizes[0] > in_sizes[1]) {
        sigma = (const float*)d_in[0];
        mu    = (const float*)d_in[1];
    }

    float* out_mu  = (float*)d_out;            // 32768 elements
    float* out_sig = out_mu + 32768;           // 8388608 elements

    fused_pool_gather_kernel<<<2048, 256>>>(mu, sigma, out_mu, out_sig);
}

// round 16
// speedup vs baseline: 1.1216x; 1.0106x over previous
#include <cuda_runtime.h>

// Fused maxpool-argmax + sigma gather — roofline configuration, finer tiling.
//
// Status: traffic is byte-minimal (~142 MB; every occupied 32B sector of the
// 256 distinct selected rows must move) and bandwidth is pinned at the
// empirical 5.0-5.3 TB/s ceiling across all R5-R15 structural variants.
// Kernel time ~= traffic/ceiling. Only remaining lever: CTA granularity
// (measured: grid 1024 -> 28.29us, 2048 -> 26.88us; spread/tail smoothing).
// This round: grid 4096 (8 rows/chunk), everything else identical to R15.
//
// Grid: 128 bc * 32 chunks = 4096 blocks, 256 threads.
__global__ __launch_bounds__(256, 8)
void fused_pool_gather_kernel(const float* __restrict__ mu,
                              const float* __restrict__ sigma,
                              float* __restrict__ out_mu,
                              float* __restrict__ out_sig) {
    __shared__ int scol[256];

    const int bc    = blockIdx.x >> 5;    // 0..127
    const int chunk = blockIdx.x & 31;    // 0..31 (8 output rows each)
    const int tid   = threadIdx.x;        // output column j

    // ---- pool/argmax for window `tid` (mu: 4KB/bc, L2-resident) ----
    {
        const int ho = tid >> 4;
        const int wo = tid & 15;
        const float* base = mu + (size_t)bc * 1024;
        const int r0 = 2 * ho;
        const int c0 = 2 * wo;

        const float v0 = base[r0 * 32 + c0];
        const float v1 = base[r0 * 32 + c0 + 1];
        const float v2 = base[(r0 + 1) * 32 + c0];
        const float v3 = base[(r0 + 1) * 32 + c0 + 1];

        float m = v0; int k = 0;
        if (v1 > m) { m = v1; k = 1; }    // strict >: first-max (jnp.argmax)
        if (v2 > m) { m = v2; k = 2; }
        if (v3 > m) { m = v3; k = 3; }

        scol[tid] = (r0 + (k >> 1)) * 32 + (c0 + (k & 1));
        if (chunk == 0) out_mu[bc * 256 + tid] = m;
    }
    __syncthreads();

    // ---- gather: out[i][tid] = sigma[bc][scol[i]][scol[tid]] ----
    const int    cj = scol[tid];
    const float* sb = sigma   + ((size_t)bc << 20);
    float*       ob = out_sig + (size_t)bc * 65536 + tid;
    const int    i0 = chunk * 8;

    int r[8];
    #pragma unroll
    for (int t = 0; t < 8; ++t)            // index prefetch (broadcast LDS)
        r[t] = scol[i0 + t];

    float v[8];
    #pragma unroll
    for (int t = 0; t < 8; ++t)            // 8 independent scattered LDGs
        v[t] = __ldcs(sb + ((size_t)r[t] << 10) + cj);

    #pragma unroll
    for (int t = 0; t < 8; ++t)            // 8 coalesced plain STG.32
        ob[(size_t)(i0 + t) * 256] = v[t];
}

extern "C" void kernel_launch(void* const* d_in, const int* in_sizes, int n_in,
                              void* d_out, int out_size) {
    const float* mu    = (const float*)d_in[0];
    const float* sigma = (const float*)d_in[1];
    if (n_in >= 2 && in_sizes[0] > in_sizes[1]) {
        sigma = (const float*)d_in[0];
        mu    = (const float*)d_in[1];
    }

    float* out_mu  = (float*)d_out;            // 32768 elements
    float* out_sig = out_mu + 32768;           // 8388608 elements

    fused_pool_gather_kernel<<<4096, 256>>>(mu, sigma, out_mu, out_sig);
}